// round 1
// baseline (speedup 1.0000x reference)
#include <cuda_runtime.h>
#include <math.h>

#define H1 256
#define W1 320
#define H2 128
#define W2 160
#define HOUT 512
#define WOUT 640
#define DEPTH 48
#define HW1 (H1*W1)
#define HW2 (H2*W2)
#define HWO (HOUT*WOUT)

// ---------------- scratch state (device globals; no allocation allowed) ----
__device__ float g_s1 [8  * HW1];
__device__ float g_s2 [16 * HW2];
__device__ float g_c1 [8  * HW1];
__device__ float g_u1 [8  * HW1];
__device__ float g_rh1[8  * HW1];
__device__ float g_c2 [16 * HW2];
__device__ float g_u2 [16 * HW2];
__device__ float g_rh2[16 * HW2];
__device__ float g_up [8  * HW1];

// ---------------- math helpers --------------------------------------------
__device__ __forceinline__ float sigf(float x) {
    return __fdividef(1.0f, 1.0f + __expf(-x));
}
__device__ __forceinline__ float tanh_fast(float x) {
    // tanh(x) = 2*sigmoid(2x) - 1   (error ~1e-7, fine vs 1e-3 budget)
    return __fdividef(2.0f, 1.0f + __expf(-2.0f * x)) - 1.0f;
}

// ---------------- shared-weight loaders ------------------------------------
// conv weight global layout: w[co_total][cin_tot][3][3]
// shared layout: ws[(ci*9 + k)*COB + co]  (co contiguous -> broadcast-friendly)
template<int CIN_TOT, int COB>
__device__ __forceinline__ void load_w_conv(float* ws, const float* __restrict__ w, int co_base) {
    const int n = CIN_TOT * 9 * COB;
    for (int i = threadIdx.x; i < n; i += blockDim.x) {
        int co   = i % COB;
        int rest = i / COB;                    // ci*9 + k
        ws[i] = w[(co_base + co) * (CIN_TOT * 9) + rest];
    }
}

// ---------------- conv accumulate core -------------------------------------
template<int CA, int CB, int COB, int STRIDE>
__device__ __forceinline__ void conv_core(float (&acc)[COB], const float* __restrict__ ws,
                                          const float* __restrict__ inA, int csA,
                                          const float* __restrict__ inB, int csB,
                                          int y, int x, int Hin, int Win) {
#pragma unroll
    for (int ky = 0; ky < 3; ky++) {
        int iy = y * STRIDE + ky - 1;
        if ((unsigned)iy >= (unsigned)Hin) continue;
#pragma unroll
        for (int kx = 0; kx < 3; kx++) {
            int ix = x * STRIDE + kx - 1;
            if ((unsigned)ix >= (unsigned)Win) continue;
            int off = iy * Win + ix;
            int k   = ky * 3 + kx;
#pragma unroll 8
            for (int ci = 0; ci < CA; ci++) {
                float v = __ldg(inA + ci * csA + off);
                const float* wp = ws + (ci * 9 + k) * COB;
#pragma unroll
                for (int co = 0; co < COB; co++) acc[co] = fmaf(wp[co], v, acc[co]);
            }
#pragma unroll 8
            for (int ci = 0; ci < CB; ci++) {
                float v = __ldg(inB + ci * csB + off);
                const float* wp = ws + ((CA + ci) * 9 + k) * COB;
#pragma unroll
                for (int co = 0; co < COB; co++) acc[co] = fmaf(wp[co], v, acc[co]);
            }
        }
    }
}

// ---------------- kernels ---------------------------------------------------
__global__ void zero_k(float* a, int n) {
    int i = blockIdx.x * blockDim.x + threadIdx.x;
    if (i < n) a[i] = 0.0f;
}

// plain conv 3x3 + relu. grid.y splits output channels into COB slabs.
template<int CIN, int COB, int STRIDE>
__global__ void conv_relu_k(const float* __restrict__ in, int cs,
                            const float* __restrict__ w, const float* __restrict__ b,
                            float* __restrict__ out,
                            int Hin, int Win, int Hout, int Wout) {
    __shared__ float ws[CIN * 9 * COB];
    int co_base = blockIdx.y * COB;
    load_w_conv<CIN, COB>(ws, w, co_base);
    __syncthreads();
    int HWo = Hout * Wout;
    int px = blockIdx.x * blockDim.x + threadIdx.x;
    if (px >= HWo) return;
    int y = px / Wout, x = px - y * Wout;
    float acc[COB];
#pragma unroll
    for (int co = 0; co < COB; co++) acc[co] = __ldg(b + co_base + co);
    conv_core<CIN, 0, COB, STRIDE>(acc, ws, in, cs, nullptr, 0, y, x, Hin, Win);
#pragma unroll
    for (int co = 0; co < COB; co++)
        out[(co_base + co) * HWo + px] = fmaxf(acc[co], 0.0f);
}

// GRU gates: conv(cat(x,h)) -> 2*CH channels, sigmoid.
// blockIdx.y==0 computes r-half and writes rh = sigmoid(r)*h
// blockIdx.y==1 computes u-half and writes u
template<int CH>
__global__ void gru_gates_k(const float* __restrict__ cx, const float* __restrict__ h,
                            const float* __restrict__ wg, const float* __restrict__ bg,
                            float* __restrict__ u_out, float* __restrict__ rh_out,
                            int Hh, int Wh) {
    __shared__ float ws[2 * CH * 9 * CH];
    int half    = blockIdx.y;
    int co_base = half * CH;
    load_w_conv<2 * CH, CH>(ws, wg, co_base);
    __syncthreads();
    int HW = Hh * Wh;
    int px = blockIdx.x * blockDim.x + threadIdx.x;
    if (px >= HW) return;
    int y = px / Wh, x = px - y * Wh;
    float acc[CH];
#pragma unroll
    for (int co = 0; co < CH; co++) acc[co] = __ldg(bg + co_base + co);
    conv_core<CH, CH, CH, 1>(acc, ws, cx, HW, h, HW, y, x, Hh, Wh);
    if (half == 0) {
#pragma unroll
        for (int co = 0; co < CH; co++)
            rh_out[co * HW + px] = sigf(acc[co]) * h[co * HW + px];
    } else {
#pragma unroll
        for (int co = 0; co < CH; co++)
            u_out[co * HW + px] = sigf(acc[co]);
    }
}

// GRU candidate: c = tanh(conv(cat(x, rh))); h = u*h + (1-u)*c  (in place)
template<int CH, int COB>
__global__ void gru_cand_k(const float* __restrict__ cx, const float* __restrict__ rh,
                           const float* __restrict__ wc, const float* __restrict__ bc,
                           const float* __restrict__ u, float* __restrict__ h,
                           int Hh, int Wh) {
    __shared__ float ws[2 * CH * 9 * COB];
    int co_base = blockIdx.y * COB;
    load_w_conv<2 * CH, COB>(ws, wc, co_base);
    __syncthreads();
    int HW = Hh * Wh;
    int px = blockIdx.x * blockDim.x + threadIdx.x;
    if (px >= HW) return;
    int y = px / Wh, x = px - y * Wh;
    float acc[COB];
#pragma unroll
    for (int co = 0; co < COB; co++) acc[co] = __ldg(bc + co_base + co);
    conv_core<CH, CH, COB, 1>(acc, ws, cx, HW, rh, HW, y, x, Hh, Wh);
#pragma unroll
    for (int co = 0; co < COB; co++) {
        float c   = tanh_fast(acc[co]);
        int  idx  = (co_base + co) * HW + px;
        float uu  = u[idx];
        h[idx] = uu * h[idx] + (1.0f - uu) * c;
    }
}

// ConvTranspose2d(k=3,s=2,p=1,output_padding=1), gather form.
// weight global layout: w[cin][cout_total][3][3]
template<int CIN, int COB, int COUT_TOT, bool ADD_RELU>
__global__ void deconv_k(const float* __restrict__ in,
                         const float* __restrict__ w, const float* __restrict__ b,
                         const float* __restrict__ add, float* __restrict__ out,
                         int Hin, int Win, int Hout, int Wout) {
    __shared__ float ws[CIN * 9 * COB];
    int co_base = blockIdx.y * COB;
    {
        const int n = CIN * 9 * COB;
        for (int i = threadIdx.x; i < n; i += blockDim.x) {
            int co   = i % COB;
            int rest = i / COB;
            int ci   = rest / 9;
            int k    = rest - ci * 9;
            ws[i] = w[(ci * COUT_TOT + co_base + co) * 9 + k];
        }
    }
    __syncthreads();
    int HWi = Hin * Win, HWo = Hout * Wout;
    int px = blockIdx.x * blockDim.x + threadIdx.x;
    if (px >= HWo) return;
    int y = px / Wout, x = px - y * Wout;
    float acc[COB];
#pragma unroll
    for (int co = 0; co < COB; co++) acc[co] = __ldg(b + co_base + co);
#pragma unroll
    for (int ky = 0; ky < 3; ky++) {
        int t = y + 1 - ky;
        if (t < 0 || (t & 1)) continue;
        int iy = t >> 1;
        if (iy >= Hin) continue;
#pragma unroll
        for (int kx = 0; kx < 3; kx++) {
            int s = x + 1 - kx;
            if (s < 0 || (s & 1)) continue;
            int ix = s >> 1;
            if (ix >= Win) continue;
            int off = iy * Win + ix;
            int k   = ky * 3 + kx;
#pragma unroll
            for (int ci = 0; ci < CIN; ci++) {
                float v = __ldg(in + ci * HWi + off);
                const float* wp = ws + (ci * 9 + k) * COB;
#pragma unroll
                for (int co = 0; co < COB; co++) acc[co] = fmaf(wp[co], v, acc[co]);
            }
        }
    }
    if (ADD_RELU) {
#pragma unroll
        for (int co = 0; co < COB; co++)
            out[(co_base + co) * HWo + px] = fmaxf(acc[co] + add[(co_base + co) * HWo + px], 0.0f);
    } else {
#pragma unroll
        for (int co = 0; co < COB; co++)
            out[(co_base + co) * HWo + px] = acc[co];
    }
}

// ---------------- launch ----------------------------------------------------
extern "C" void kernel_launch(void* const* d_in, const int* in_sizes, int n_in,
                              void* d_out, int out_size) {
    const float* vol  = (const float*)d_in[0];
    const float* c1w  = (const float*)d_in[1];
    const float* c1b  = (const float*)d_in[2];
    const float* g1wg = (const float*)d_in[3];
    const float* g1bg = (const float*)d_in[4];
    const float* g1wc = (const float*)d_in[5];
    const float* g1bc = (const float*)d_in[6];
    const float* c2w  = (const float*)d_in[7];
    const float* c2b  = (const float*)d_in[8];
    const float* g2wg = (const float*)d_in[9];
    const float* g2bg = (const float*)d_in[10];
    const float* g2wc = (const float*)d_in[11];
    const float* g2bc = (const float*)d_in[12];
    const float* u1w  = (const float*)d_in[13];
    const float* u1b  = (const float*)d_in[14];
    const float* u2w  = (const float*)d_in[15];
    const float* u2b  = (const float*)d_in[16];
    float* out = (float*)d_out;

    float *s1, *s2, *c1, *u1, *rh1, *c2, *u2, *rh2, *up;
    cudaGetSymbolAddress((void**)&s1,  g_s1);
    cudaGetSymbolAddress((void**)&s2,  g_s2);
    cudaGetSymbolAddress((void**)&c1,  g_c1);
    cudaGetSymbolAddress((void**)&u1,  g_u1);
    cudaGetSymbolAddress((void**)&rh1, g_rh1);
    cudaGetSymbolAddress((void**)&c2,  g_c2);
    cudaGetSymbolAddress((void**)&u2,  g_u2);
    cudaGetSymbolAddress((void**)&rh2, g_rh2);
    cudaGetSymbolAddress((void**)&up,  g_up);

    const int TB = 256;
    zero_k<<<(8 * HW1 + TB - 1) / TB, TB>>>(s1, 8 * HW1);
    zero_k<<<(16 * HW2 + TB - 1) / TB, TB>>>(s2, 16 * HW2);

    int nb1 = (HW1 + TB - 1) / TB;   // 320
    int nb2 = (HW2 + TB - 1) / TB;   // 80
    int nbo = (HWO + TB - 1) / TB;   // 1280

    for (int d = 0; d < DEPTH; d++) {
        // c1 = relu(conv1(cost_d))
        conv_relu_k<32, 8, 1><<<dim3(nb1, 1), TB>>>(vol + (long)d * HW1, DEPTH * HW1,
                                                    c1w, c1b, c1, H1, W1, H1, W1);
        // s1 = GRU1(c1, s1)
        gru_gates_k<8><<<dim3(nb1, 2), TB>>>(c1, s1, g1wg, g1bg, u1, rh1, H1, W1);
        gru_cand_k<8, 8><<<dim3(nb1, 1), TB>>>(c1, rh1, g1wc, g1bc, u1, s1, H1, W1);
        // c2 = relu(conv2(s1)) stride 2
        conv_relu_k<8, 8, 2><<<dim3(nb2, 2), TB>>>(s1, HW1, c2w, c2b, c2, H1, W1, H2, W2);
        // s2 = GRU2(c2, s2)
        gru_gates_k<16><<<dim3(nb2, 2), TB>>>(c2, s2, g2wg, g2bg, u2, rh2, H2, W2);
        gru_cand_k<16, 8><<<dim3(nb2, 2), TB>>>(c2, rh2, g2wc, g2bc, u2, s2, H2, W2);
        // up = relu(deconv(s2) + s1)
        deconv_k<16, 8, 8, true><<<dim3(nb1, 1), TB>>>(s2, u1w, u1b, s1, up, H2, W2, H1, W1);
        // out_d = deconv(up)
        deconv_k<8, 1, 1, false><<<dim3(nbo, 1), TB>>>(up, u2w, u2b, nullptr,
                                                       out + (long)d * HWO, H1, W1, HOUT, WOUT);
    }
}